// round 1
// baseline (speedup 1.0000x reference)
#include <cuda_runtime.h>
#include <cuda_bf16.h>

// Problem constants
#define T_GIVEN   2048      // tokens carried in qkv
#define T_CACHE   1024      // prepended cache tokens
#define T_FULL    (T_GIVEN + T_CACHE)   // 3072
#define C_EMBED   1024
#define N_HEADS   16
#define HEAD_D    64
#define ROW3C     (3 * C_EMBED)         // 3072 floats per input row

// Tiling
#define BQ        64        // queries per CTA
#define BK        32        // keys per smem tile
#define NTHREADS  128       // 2 threads per query

__global__ __launch_bounds__(NTHREADS, 3)
void flash_attn_fp32_kernel(const float* __restrict__ qkv,
                            const float* __restrict__ cache,
                            float* __restrict__ out)
{
    // K/V tiles: BK rows x 64 floats = 16 float4 per row
    __shared__ float4 ksm[BK * 16];
    __shared__ float4 vsm[BK * 16];

    const int qb   = blockIdx.x;          // 0..31
    const int h    = blockIdx.y;          // 0..15
    const int tid  = threadIdx.x;
    const int qi   = tid >> 1;            // query within block, 0..63
    const int half = tid & 1;             // which 32-dim half this thread owns

    const int tq = T_CACHE + qb * BQ + qi;    // global query position (>= 1024)

    // ---- load and pre-scale q (this thread's 32 dims) ----
    const float scale = 0.125f;               // 1/sqrt(64)
    const float4* qrow = reinterpret_cast<const float4*>(
        qkv + (size_t)(tq - T_CACHE) * ROW3C + h * HEAD_D + half * 32);
    float4 q[8];
#pragma unroll
    for (int i = 0; i < 8; ++i) {
        float4 v = qrow[i];
        v.x *= scale; v.y *= scale; v.z *= scale; v.w *= scale;
        q[i] = v;
    }

    float acc[32];
#pragma unroll
    for (int i = 0; i < 32; ++i) acc[i] = 0.f;
    float m = -1e30f;
    float l = 0.f;

    const int nkeys   = T_CACHE + qb * BQ + BQ;   // max query pos in CTA + 1
    const int nblocks = nkeys / BK;               // exact (multiples of 32)

    for (int kb = 0; kb < nblocks; ++kb) {
        const int s0 = kb * BK;

        // ---- cooperative load of K/V tile ----
        __syncthreads();
#pragma unroll
        for (int it = 0; it < (BK * 16) / NTHREADS; ++it) {
            int i   = tid + it * NTHREADS;        // 0..511
            int row = i >> 4;
            int c4  = i & 15;
            int s   = s0 + row;
            const float* base = (s < T_CACHE)
                ? (cache + (size_t)s * ROW3C)
                : (qkv + (size_t)(s - T_CACHE) * ROW3C);
            ksm[i] = *reinterpret_cast<const float4*>(base + C_EMBED     + h * HEAD_D + c4 * 4);
            vsm[i] = *reinterpret_cast<const float4*>(base + 2 * C_EMBED + h * HEAD_D + c4 * 4);
        }
        __syncthreads();

        // ---- scores for BK keys ----
        float sc[BK];
#pragma unroll
        for (int j = 0; j < BK; ++j) {
            const float4* kr = &ksm[j * 16 + half * 8];
            float s_ = 0.f;
#pragma unroll
            for (int i = 0; i < 8; ++i) {
                float4 kv = kr[i];
                s_ = fmaf(q[i].x, kv.x, s_);
                s_ = fmaf(q[i].y, kv.y, s_);
                s_ = fmaf(q[i].z, kv.z, s_);
                s_ = fmaf(q[i].w, kv.w, s_);
            }
            // combine the two halves of the dot product
            s_ += __shfl_xor_sync(0xffffffffu, s_, 1);
            sc[j] = (s0 + j <= tq) ? s_ : -1e30f;
        }

        // ---- online softmax update ----
        float bm = sc[0];
#pragma unroll
        for (int j = 1; j < BK; ++j) bm = fmaxf(bm, sc[j]);
        float mnew  = fmaxf(m, bm);
        float alpha = __expf(m - mnew);
        l *= alpha;
#pragma unroll
        for (int i = 0; i < 32; ++i) acc[i] *= alpha;
        m = mnew;

#pragma unroll
        for (int j = 0; j < BK; ++j) {
            float p = __expf(sc[j] - mnew);
            l += p;
            const float4* vr = &vsm[j * 16 + half * 8];
#pragma unroll
            for (int i = 0; i < 8; ++i) {
                float4 vv = vr[i];
                acc[4 * i + 0] = fmaf(p, vv.x, acc[4 * i + 0]);
                acc[4 * i + 1] = fmaf(p, vv.y, acc[4 * i + 1]);
                acc[4 * i + 2] = fmaf(p, vv.z, acc[4 * i + 2]);
                acc[4 * i + 3] = fmaf(p, vv.w, acc[4 * i + 3]);
            }
        }
    }

    // ---- epilogue ----
    const float inv = 1.f / l;
    float4* orow = reinterpret_cast<float4*>(
        out + (size_t)(tq - T_CACHE) * C_EMBED + h * HEAD_D + half * 32);
#pragma unroll
    for (int i = 0; i < 8; ++i) {
        float4 o;
        o.x = acc[4 * i + 0] * inv;
        o.y = acc[4 * i + 1] * inv;
        o.z = acc[4 * i + 2] * inv;
        o.w = acc[4 * i + 3] * inv;
        orow[i] = o;
    }
}

extern "C" void kernel_launch(void* const* d_in, const int* in_sizes, int n_in,
                              void* d_out, int out_size)
{
    const float* qkv   = (const float*)d_in[0];   // [2048, 3072]
    const float* cache = (const float*)d_in[1];   // [1024, 3072]
    float* out = (float*)d_out;                   // [2048, 1024]

    dim3 grid(T_GIVEN / BQ, N_HEADS);             // (32, 16)
    flash_attn_fp32_kernel<<<grid, NTHREADS>>>(qkv, cache, out);
}

// round 2
// speedup vs baseline: 1.8322x; 1.8322x over previous
#include <cuda_runtime.h>

#define T_CACHE 1024
#define ROW3C   3072
#define CEMB    1024
#define BQ      64          // queries per phase
#define BK      32          // keys per smem tile
#define CH      8           // score-chunk size
#define NTH     128
#define NB      32          // number of 64-query blocks (2048/64)
#define NPAIR   16          // balanced pairs

typedef unsigned long long u64;

__device__ __forceinline__ u64 fma2(u64 a, u64 b, u64 c) {
    u64 d; asm("fma.rn.f32x2 %0, %1, %2, %3;" : "=l"(d) : "l"(a), "l"(b), "l"(c)); return d;
}
__device__ __forceinline__ u64 mul2(u64 a, u64 b) {
    u64 d; asm("mul.rn.f32x2 %0, %1, %2;" : "=l"(d) : "l"(a), "l"(b)); return d;
}
__device__ __forceinline__ u64 pack2(float x) {
    u64 d; asm("mov.b64 %0, {%1, %1};" : "=l"(d) : "f"(x)); return d;
}
__device__ __forceinline__ u64 pack2p(float x, float y) {
    u64 d; asm("mov.b64 %0, {%1, %2};" : "=l"(d) : "f"(x), "f"(y)); return d;
}
__device__ __forceinline__ float hadd2(u64 a) {
    float lo, hi; asm("mov.b64 {%0, %1}, %2;" : "=f"(lo), "=f"(hi) : "l"(a)); return lo + hi;
}

// Process one CH-key chunk of the current tile.
template<bool MASK>
__device__ __forceinline__ void do_chunk(
    const ulonglong2* __restrict__ ksm, const ulonglong2* __restrict__ vsm,
    int c0, int s0, int sub, int tq0,
    const u64 q[2][8], u64 acc[2][8], float m[2], float l[2])
{
    float sc[2][CH];

#pragma unroll
    for (int j = 0; j < CH; ++j) {
        const int jj = c0 + j;
        const ulonglong2 ka = ksm[jj * 16 + sub];
        const ulonglong2 kb = ksm[jj * 16 + sub + 4];
        const ulonglong2 kc = ksm[jj * 16 + sub + 8];
        const ulonglong2 kd = ksm[jj * 16 + sub + 12];
#pragma unroll
        for (int qq = 0; qq < 2; ++qq) {
            u64 t = mul2(q[qq][0], ka.x);
            t = fma2(q[qq][1], ka.y, t);
            t = fma2(q[qq][2], kb.x, t);
            t = fma2(q[qq][3], kb.y, t);
            t = fma2(q[qq][4], kc.x, t);
            t = fma2(q[qq][5], kc.y, t);
            t = fma2(q[qq][6], kd.x, t);
            t = fma2(q[qq][7], kd.y, t);
            float s = hadd2(t);
            s += __shfl_xor_sync(0xffffffffu, s, 1);
            s += __shfl_xor_sync(0xffffffffu, s, 2);
            if (MASK)
                sc[qq][j] = (s0 + jj <= tq0 + qq) ? s : -1e30f;
            else
                sc[qq][j] = s;
        }
    }

    // online softmax update
#pragma unroll
    for (int qq = 0; qq < 2; ++qq) {
        float bm = sc[qq][0];
#pragma unroll
        for (int j = 1; j < CH; ++j) bm = fmaxf(bm, sc[qq][j]);
        const float mn = fmaxf(m[qq], bm);
        const float al = __expf(m[qq] - mn);
        m[qq] = mn;
        l[qq] *= al;
        const u64 al2 = pack2(al);
#pragma unroll
        for (int u = 0; u < 8; ++u) acc[qq][u] = mul2(acc[qq][u], al2);
#pragma unroll
        for (int j = 0; j < CH; ++j) {
            const float p = __expf(sc[qq][j] - mn);
            l[qq] += p;
            sc[qq][j] = p;
        }
    }

    // PV accumulate
#pragma unroll
    for (int j = 0; j < CH; ++j) {
        const int jj = c0 + j;
        const ulonglong2 va = vsm[jj * 16 + sub];
        const ulonglong2 vb = vsm[jj * 16 + sub + 4];
        const ulonglong2 vc = vsm[jj * 16 + sub + 8];
        const ulonglong2 vd = vsm[jj * 16 + sub + 12];
#pragma unroll
        for (int qq = 0; qq < 2; ++qq) {
            const u64 p2 = pack2(sc[qq][j]);
            acc[qq][0] = fma2(p2, va.x, acc[qq][0]);
            acc[qq][1] = fma2(p2, va.y, acc[qq][1]);
            acc[qq][2] = fma2(p2, vb.x, acc[qq][2]);
            acc[qq][3] = fma2(p2, vb.y, acc[qq][3]);
            acc[qq][4] = fma2(p2, vc.x, acc[qq][4]);
            acc[qq][5] = fma2(p2, vc.y, acc[qq][5]);
            acc[qq][6] = fma2(p2, vd.x, acc[qq][6]);
            acc[qq][7] = fma2(p2, vd.y, acc[qq][7]);
        }
    }
}

// One 64-query block (one "phase") done by the whole CTA.
__device__ __forceinline__ void run_phase(
    int qb, int h,
    const float* __restrict__ qkv, const float* __restrict__ cache,
    float* __restrict__ out,
    ulonglong2* ksm, ulonglong2* vsm, int tid)
{
    const int sub = tid & 3;      // 16-dim slice: float4 chunks {sub, sub+4, sub+8, sub+12}
    const int grp = tid >> 2;     // 0..31 -> 2 queries each
    const int ql  = qb * BQ + grp * 2;   // local query row (0..2047)
    const int tq0 = T_CACHE + ql;        // global position of qq=0

    // load + pre-scale q
    const float scl = 0.125f;
    u64 q[2][8];
#pragma unroll
    for (int qq = 0; qq < 2; ++qq) {
        const float4* qr = reinterpret_cast<const float4*>(
            qkv + (size_t)(ql + qq) * ROW3C + h * 64);
#pragma unroll
        for (int i = 0; i < 4; ++i) {
            float4 v = qr[sub + 4 * i];
            q[qq][2 * i]     = pack2p(v.x * scl, v.y * scl);
            q[qq][2 * i + 1] = pack2p(v.z * scl, v.w * scl);
        }
    }

    u64 acc[2][8];
#pragma unroll
    for (int qq = 0; qq < 2; ++qq)
#pragma unroll
        for (int u = 0; u < 8; ++u) acc[qq][u] = 0ull;
    float m[2] = {-1e30f, -1e30f};
    float l[2] = {0.f, 0.f};

    const int nkeys  = T_CACHE + qb * BQ + BQ;
    const int ntiles = nkeys / BK;      // exact
    const int nfull  = ntiles - 2;      // last BQ keys need the causal mask

    for (int t = 0; t < ntiles; ++t) {
        const int s0 = t * BK;
        __syncthreads();
        // tiles never straddle the cache/qkv boundary (1024 % 32 == 0)
        const float* base = (s0 < T_CACHE)
            ? (cache + (size_t)s0 * ROW3C)
            : (qkv + (size_t)(s0 - T_CACHE) * ROW3C);
#pragma unroll
        for (int it = 0; it < 4; ++it) {
            const int idx = tid + it * NTH;   // 0..511
            const int row = idx >> 4;
            const int c   = idx & 15;
            const float* rp = base + (size_t)row * ROW3C + h * 64 + c * 4;
            ksm[idx] = *reinterpret_cast<const ulonglong2*>(rp + CEMB);
            vsm[idx] = *reinterpret_cast<const ulonglong2*>(rp + 2 * CEMB);
        }
        __syncthreads();

        if (t < nfull) {
#pragma unroll
            for (int c0 = 0; c0 < BK; c0 += CH)
                do_chunk<false>(ksm, vsm, c0, s0, sub, tq0, q, acc, m, l);
        } else {
#pragma unroll
            for (int c0 = 0; c0 < BK; c0 += CH)
                do_chunk<true>(ksm, vsm, c0, s0, sub, tq0, q, acc, m, l);
        }
    }

    // epilogue
#pragma unroll
    for (int qq = 0; qq < 2; ++qq) {
        const u64 inv2 = pack2(1.f / l[qq]);
        ulonglong2* orow = reinterpret_cast<ulonglong2*>(
            out + (size_t)(ql + qq) * CEMB + h * 64);
#pragma unroll
        for (int i = 0; i < 4; ++i) {
            ulonglong2 o;
            o.x = mul2(acc[qq][2 * i], inv2);
            o.y = mul2(acc[qq][2 * i + 1], inv2);
            orow[sub + 4 * i] = o;
        }
    }
}

__global__ __launch_bounds__(NTH, 3)
void fa2_kernel(const float* __restrict__ qkv,
                const float* __restrict__ cache,
                float* __restrict__ out)
{
    __shared__ ulonglong2 ksm[BK * 16];
    __shared__ ulonglong2 vsm[BK * 16];

    const int qbp = blockIdx.x;   // 0..15
    const int h   = blockIdx.y;   // 0..15
    const int tid = threadIdx.x;

    // balanced pair: (qbp) + (31 - qbp) => constant 130 tiles per CTA
    run_phase(qbp, h, qkv, cache, out, ksm, vsm, tid);
    run_phase(NB - 1 - qbp, h, qkv, cache, out, ksm, vsm, tid);
}

extern "C" void kernel_launch(void* const* d_in, const int* in_sizes, int n_in,
                              void* d_out, int out_size)
{
    const float* qkv   = (const float*)d_in[0];   // [2048, 3072]
    const float* cache = (const float*)d_in[1];   // [1024, 3072]
    float* out = (float*)d_out;                   // [2048, 1024]

    dim3 grid(NPAIR, 16);    // (16 pairs, 16 heads)
    fa2_kernel<<<grid, NTH>>>(qkv, cache, out);
}

// round 3
// speedup vs baseline: 1.9394x; 1.0585x over previous
#include <cuda_runtime.h>

#define T_CACHE 1024
#define ROW3C   3072
#define CEMB    1024
#define BQ      64          // queries per phase
#define BK      32          // keys per smem tile
#define CH      8           // score-chunk size
#define NTH     128
#define NB      32          // number of 64-query blocks (2048/64)
#define NPAIR   16          // balanced pairs

typedef unsigned long long u64;

__device__ __forceinline__ u64 fma2(u64 a, u64 b, u64 c) {
    u64 d; asm("fma.rn.f32x2 %0, %1, %2, %3;" : "=l"(d) : "l"(a), "l"(b), "l"(c)); return d;
}
__device__ __forceinline__ u64 mul2(u64 a, u64 b) {
    u64 d; asm("mul.rn.f32x2 %0, %1, %2;" : "=l"(d) : "l"(a), "l"(b)); return d;
}
__device__ __forceinline__ u64 pack2(float x) {
    u64 d; asm("mov.b64 %0, {%1, %1};" : "=l"(d) : "f"(x)); return d;
}
__device__ __forceinline__ u64 pack2p(float x, float y) {
    u64 d; asm("mov.b64 %0, {%1, %2};" : "=l"(d) : "f"(x), "f"(y)); return d;
}
__device__ __forceinline__ float hadd2(u64 a) {
    float lo, hi; asm("mov.b64 {%0, %1}, %2;" : "=f"(lo), "=f"(hi) : "l"(a)); return lo + hi;
}

// Process one CH-key chunk of the current tile.
template<bool MASK>
__device__ __forceinline__ void do_chunk(
    const ulonglong2* __restrict__ ksm, const ulonglong2* __restrict__ vsm,
    int c0, int s0, int sub, int tq0,
    const u64 q[2][8], u64 acc[2][8], float m[2], float l[2])
{
    float sc[2][CH];

#pragma unroll
    for (int j = 0; j < CH; ++j) {
        const int jj = c0 + j;
        const ulonglong2 ka = ksm[jj * 16 + sub];
        const ulonglong2 kb = ksm[jj * 16 + sub + 4];
        const ulonglong2 kc = ksm[jj * 16 + sub + 8];
        const ulonglong2 kd = ksm[jj * 16 + sub + 12];
#pragma unroll
        for (int qq = 0; qq < 2; ++qq) {
            u64 t = mul2(q[qq][0], ka.x);
            t = fma2(q[qq][1], ka.y, t);
            t = fma2(q[qq][2], kb.x, t);
            t = fma2(q[qq][3], kb.y, t);
            t = fma2(q[qq][4], kc.x, t);
            t = fma2(q[qq][5], kc.y, t);
            t = fma2(q[qq][6], kd.x, t);
            t = fma2(q[qq][7], kd.y, t);
            float s = hadd2(t);
            s += __shfl_xor_sync(0xffffffffu, s, 1);
            s += __shfl_xor_sync(0xffffffffu, s, 2);
            if (MASK)
                sc[qq][j] = (s0 + jj <= tq0 + qq) ? s : -1e30f;
            else
                sc[qq][j] = s;
        }
    }

    // online softmax update
#pragma unroll
    for (int qq = 0; qq < 2; ++qq) {
        float bm = sc[qq][0];
#pragma unroll
        for (int j = 1; j < CH; ++j) bm = fmaxf(bm, sc[qq][j]);
        const float mn = fmaxf(m[qq], bm);
        const float al = __expf(m[qq] - mn);
        m[qq] = mn;
        l[qq] *= al;
        const u64 al2 = pack2(al);
#pragma unroll
        for (int u = 0; u < 8; ++u) acc[qq][u] = mul2(acc[qq][u], al2);
#pragma unroll
        for (int j = 0; j < CH; ++j) {
            const float p = __expf(sc[qq][j] - mn);
            l[qq] += p;
            sc[qq][j] = p;
        }
    }

    // PV accumulate
#pragma unroll
    for (int j = 0; j < CH; ++j) {
        const int jj = c0 + j;
        const ulonglong2 va = vsm[jj * 16 + sub];
        const ulonglong2 vb = vsm[jj * 16 + sub + 4];
        const ulonglong2 vc = vsm[jj * 16 + sub + 8];
        const ulonglong2 vd = vsm[jj * 16 + sub + 12];
#pragma unroll
        for (int qq = 0; qq < 2; ++qq) {
            const u64 p2 = pack2(sc[qq][j]);
            acc[qq][0] = fma2(p2, va.x, acc[qq][0]);
            acc[qq][1] = fma2(p2, va.y, acc[qq][1]);
            acc[qq][2] = fma2(p2, vb.x, acc[qq][2]);
            acc[qq][3] = fma2(p2, vb.y, acc[qq][3]);
            acc[qq][4] = fma2(p2, vc.x, acc[qq][4]);
            acc[qq][5] = fma2(p2, vc.y, acc[qq][5]);
            acc[qq][6] = fma2(p2, vd.x, acc[qq][6]);
            acc[qq][7] = fma2(p2, vd.y, acc[qq][7]);
        }
    }
}

// One 64-query block (one "phase") done by the whole CTA.
__device__ __forceinline__ void run_phase(
    int qb, int h,
    const float* __restrict__ qkv, const float* __restrict__ cache,
    float* __restrict__ out,
    ulonglong2* ksm, ulonglong2* vsm, int tid)
{
    const int sub = tid & 3;      // 16-dim slice: float4 chunks {sub, sub+4, sub+8, sub+12}
    const int grp = tid >> 2;     // 0..31 -> 2 queries each
    const int ql  = qb * BQ + grp * 2;   // local query row (0..2047)
    const int tq0 = T_CACHE + ql;        // global position of qq=0

    // load + pre-scale q
    const float scl = 0.125f;
    u64 q[2][8];
#pragma unroll
    for (int qq = 0; qq < 2; ++qq) {
        const float4* qr = reinterpret_cast<const float4*>(
            qkv + (size_t)(ql + qq) * ROW3C + h * 64);
#pragma unroll
        for (int i = 0; i < 4; ++i) {
            float4 v = qr[sub + 4 * i];
            q[qq][2 * i]     = pack2p(v.x * scl, v.y * scl);
            q[qq][2 * i + 1] = pack2p(v.z * scl, v.w * scl);
        }
    }

    u64 acc[2][8];
#pragma unroll
    for (int qq = 0; qq < 2; ++qq)
#pragma unroll
        for (int u = 0; u < 8; ++u) acc[qq][u] = 0ull;
    float m[2] = {-1e30f, -1e30f};
    float l[2] = {0.f, 0.f};

    const int nkeys  = T_CACHE + qb * BQ + BQ;
    const int ntiles = nkeys / BK;      // exact
    const int nfull  = ntiles - 2;      // last BQ keys need the causal mask

    for (int t = 0; t < ntiles; ++t) {
        const int s0 = t * BK;
        __syncthreads();
        // tiles never straddle the cache/qkv boundary (1024 % 32 == 0)
        const float* base = (s0 < T_CACHE)
            ? (cache + (size_t)s0 * ROW3C)
            : (qkv + (size_t)(s0 - T_CACHE) * ROW3C);
#pragma unroll
        for (int it = 0; it < 4; ++it) {
            const int idx = tid + it * NTH;   // 0..511
            const int row = idx >> 4;
            const int c   = idx & 15;
            const float* rp = base + (size_t)row * ROW3C + h * 64 + c * 4;
            ksm[idx] = *reinterpret_cast<const ulonglong2*>(rp + CEMB);
            vsm[idx] = *reinterpret_cast<const ulonglong2*>(rp + 2 * CEMB);
        }
        __syncthreads();

        if (t < nfull) {
#pragma unroll
            for (int c0 = 0; c0 < BK; c0 += CH)
                do_chunk<false>(ksm, vsm, c0, s0, sub, tq0, q, acc, m, l);
        } else {
#pragma unroll
            for (int c0 = 0; c0 < BK; c0 += CH)
                do_chunk<true>(ksm, vsm, c0, s0, sub, tq0, q, acc, m, l);
        }
    }

    // epilogue
#pragma unroll
    for (int qq = 0; qq < 2; ++qq) {
        const u64 inv2 = pack2(1.f / l[qq]);
        ulonglong2* orow = reinterpret_cast<ulonglong2*>(
            out + (size_t)(ql + qq) * CEMB + h * 64);
#pragma unroll
        for (int i = 0; i < 4; ++i) {
            ulonglong2 o;
            o.x = mul2(acc[qq][2 * i], inv2);
            o.y = mul2(acc[qq][2 * i + 1], inv2);
            orow[sub + 4 * i] = o;
        }
    }
}

__global__ __launch_bounds__(NTH, 3)
void fa2_kernel(const float* __restrict__ qkv,
                const float* __restrict__ cache,
                float* __restrict__ out)
{
    __shared__ ulonglong2 ksm[BK * 16];
    __shared__ ulonglong2 vsm[BK * 16];

    const int qbp = blockIdx.x;   // 0..15
    const int h   = blockIdx.y;   // 0..15
    const int tid = threadIdx.x;

    // balanced pair: (qbp) + (31 - qbp) => constant 130 tiles per CTA
    run_phase(qbp, h, qkv, cache, out, ksm, vsm, tid);
    run_phase(NB - 1 - qbp, h, qkv, cache, out, ksm, vsm, tid);
}

extern "C" void kernel_launch(void* const* d_in, const int* in_sizes, int n_in,
                              void* d_out, int out_size)
{
    const float* qkv   = (const float*)d_in[0];   // [2048, 3072]
    const float* cache = (const float*)d_in[1];   // [1024, 3072]
    float* out = (float*)d_out;                   // [2048, 1024]

    dim3 grid(NPAIR, 16);    // (16 pairs, 16 heads)
    fa2_kernel<<<grid, NTH>>>(qkv, cache, out);
}

// round 4
// speedup vs baseline: 1.9471x; 1.0040x over previous
#include <cuda_runtime.h>

#define T_CACHE 1024
#define ROW3C   3072
#define CEMB    1024
#define BQ      64          // queries per phase
#define BK      32          // keys per smem tile
#define CH      8           // score-chunk size
#define NTH     128
#define NB      32          // number of 64-query blocks (2048/64)
#define NPAIR   16          // balanced pairs

typedef unsigned long long u64;

__device__ __forceinline__ u64 fma2(u64 a, u64 b, u64 c) {
    u64 d; asm("fma.rn.f32x2 %0, %1, %2, %3;" : "=l"(d) : "l"(a), "l"(b), "l"(c)); return d;
}
__device__ __forceinline__ u64 mul2(u64 a, u64 b) {
    u64 d; asm("mul.rn.f32x2 %0, %1, %2;" : "=l"(d) : "l"(a), "l"(b)); return d;
}
__device__ __forceinline__ u64 pack2(float x) {
    u64 d; asm("mov.b64 %0, {%1, %1};" : "=l"(d) : "f"(x)); return d;
}
__device__ __forceinline__ u64 pack2p(float x, float y) {
    u64 d; asm("mov.b64 %0, {%1, %2};" : "=l"(d) : "f"(x), "f"(y)); return d;
}
__device__ __forceinline__ float hadd2(u64 a) {
    float lo, hi; asm("mov.b64 {%0, %1}, %2;" : "=f"(lo), "=f"(hi) : "l"(a)); return lo + hi;
}

// Process one CH-key chunk of the current tile.
template<bool MASK>
__device__ __forceinline__ void do_chunk(
    const ulonglong2* __restrict__ ksm, const ulonglong2* __restrict__ vsm,
    int c0, int s0, int sub, int tq0,
    const u64 q[2][8], u64 acc[2][8], float m[2], float l[2])
{
    float sc[2][CH];

#pragma unroll
    for (int j = 0; j < CH; ++j) {
        const int jj = c0 + j;
        const ulonglong2 ka = ksm[jj * 16 + sub];
        const ulonglong2 kb = ksm[jj * 16 + sub + 4];
        const ulonglong2 kc = ksm[jj * 16 + sub + 8];
        const ulonglong2 kd = ksm[jj * 16 + sub + 12];
#pragma unroll
        for (int qq = 0; qq < 2; ++qq) {
            u64 t = mul2(q[qq][0], ka.x);
            t = fma2(q[qq][1], ka.y, t);
            t = fma2(q[qq][2], kb.x, t);
            t = fma2(q[qq][3], kb.y, t);
            t = fma2(q[qq][4], kc.x, t);
            t = fma2(q[qq][5], kc.y, t);
            t = fma2(q[qq][6], kd.x, t);
            t = fma2(q[qq][7], kd.y, t);
            float s = hadd2(t);
            s += __shfl_xor_sync(0xffffffffu, s, 1);
            s += __shfl_xor_sync(0xffffffffu, s, 2);
            if (MASK)
                sc[qq][j] = (s0 + jj <= tq0 + qq) ? s : -1e30f;
            else
                sc[qq][j] = s;
        }
    }

    // online softmax update
#pragma unroll
    for (int qq = 0; qq < 2; ++qq) {
        float bm = sc[qq][0];
#pragma unroll
        for (int j = 1; j < CH; ++j) bm = fmaxf(bm, sc[qq][j]);
        const float mn = fmaxf(m[qq], bm);
        const float al = __expf(m[qq] - mn);
        m[qq] = mn;
        l[qq] *= al;
        const u64 al2 = pack2(al);
#pragma unroll
        for (int u = 0; u < 8; ++u) acc[qq][u] = mul2(acc[qq][u], al2);
#pragma unroll
        for (int j = 0; j < CH; ++j) {
            const float p = __expf(sc[qq][j] - mn);
            l[qq] += p;
            sc[qq][j] = p;
        }
    }

    // PV accumulate
#pragma unroll
    for (int j = 0; j < CH; ++j) {
        const int jj = c0 + j;
        const ulonglong2 va = vsm[jj * 16 + sub];
        const ulonglong2 vb = vsm[jj * 16 + sub + 4];
        const ulonglong2 vc = vsm[jj * 16 + sub + 8];
        const ulonglong2 vd = vsm[jj * 16 + sub + 12];
#pragma unroll
        for (int qq = 0; qq < 2; ++qq) {
            const u64 p2 = pack2(sc[qq][j]);
            acc[qq][0] = fma2(p2, va.x, acc[qq][0]);
            acc[qq][1] = fma2(p2, va.y, acc[qq][1]);
            acc[qq][2] = fma2(p2, vb.x, acc[qq][2]);
            acc[qq][3] = fma2(p2, vb.y, acc[qq][3]);
            acc[qq][4] = fma2(p2, vc.x, acc[qq][4]);
            acc[qq][5] = fma2(p2, vc.y, acc[qq][5]);
            acc[qq][6] = fma2(p2, vd.x, acc[qq][6]);
            acc[qq][7] = fma2(p2, vd.y, acc[qq][7]);
        }
    }
}

// One 64-query block (one "phase") done by the whole CTA.
__device__ __forceinline__ void run_phase(
    int qb, int h,
    const float* __restrict__ qkv, const float* __restrict__ cache,
    float* __restrict__ out,
    ulonglong2* ksm, ulonglong2* vsm, int tid)
{
    const int sub = tid & 3;      // 16-dim slice: float4 chunks {sub, sub+4, sub+8, sub+12}
    const int grp = tid >> 2;     // 0..31 -> 2 queries each
    const int ql  = qb * BQ + grp * 2;   // local query row (0..2047)
    const int tq0 = T_CACHE + ql;        // global position of qq=0

    // load + pre-scale q
    const float scl = 0.125f;
    u64 q[2][8];
#pragma unroll
    for (int qq = 0; qq < 2; ++qq) {
        const float4* qr = reinterpret_cast<const float4*>(
            qkv + (size_t)(ql + qq) * ROW3C + h * 64);
#pragma unroll
        for (int i = 0; i < 4; ++i) {
            float4 v = qr[sub + 4 * i];
            q[qq][2 * i]     = pack2p(v.x * scl, v.y * scl);
            q[qq][2 * i + 1] = pack2p(v.z * scl, v.w * scl);
        }
    }

    u64 acc[2][8];
#pragma unroll
    for (int qq = 0; qq < 2; ++qq)
#pragma unroll
        for (int u = 0; u < 8; ++u) acc[qq][u] = 0ull;
    float m[2] = {-1e30f, -1e30f};
    float l[2] = {0.f, 0.f};

    const int nkeys  = T_CACHE + qb * BQ + BQ;
    const int ntiles = nkeys / BK;      // exact
    const int nfull  = ntiles - 2;      // last BQ keys need the causal mask

    for (int t = 0; t < ntiles; ++t) {
        const int s0 = t * BK;
        __syncthreads();
        // tiles never straddle the cache/qkv boundary (1024 % 32 == 0)
        const float* base = (s0 < T_CACHE)
            ? (cache + (size_t)s0 * ROW3C)
            : (qkv + (size_t)(s0 - T_CACHE) * ROW3C);
#pragma unroll
        for (int it = 0; it < 4; ++it) {
            const int idx = tid + it * NTH;   // 0..511
            const int row = idx >> 4;
            const int c   = idx & 15;
            const float* rp = base + (size_t)row * ROW3C + h * 64 + c * 4;
            ksm[idx] = *reinterpret_cast<const ulonglong2*>(rp + CEMB);
            vsm[idx] = *reinterpret_cast<const ulonglong2*>(rp + 2 * CEMB);
        }
        __syncthreads();

        if (t < nfull) {
#pragma unroll
            for (int c0 = 0; c0 < BK; c0 += CH)
                do_chunk<false>(ksm, vsm, c0, s0, sub, tq0, q, acc, m, l);
        } else {
#pragma unroll
            for (int c0 = 0; c0 < BK; c0 += CH)
                do_chunk<true>(ksm, vsm, c0, s0, sub, tq0, q, acc, m, l);
        }
    }

    // epilogue
#pragma unroll
    for (int qq = 0; qq < 2; ++qq) {
        const u64 inv2 = pack2(1.f / l[qq]);
        ulonglong2* orow = reinterpret_cast<ulonglong2*>(
            out + (size_t)(ql + qq) * CEMB + h * 64);
#pragma unroll
        for (int i = 0; i < 4; ++i) {
            ulonglong2 o;
            o.x = mul2(acc[qq][2 * i], inv2);
            o.y = mul2(acc[qq][2 * i + 1], inv2);
            orow[sub + 4 * i] = o;
        }
    }
}

__global__ __launch_bounds__(NTH, 3)
void fa2_kernel(const float* __restrict__ qkv,
                const float* __restrict__ cache,
                float* __restrict__ out)
{
    __shared__ ulonglong2 ksm[BK * 16];
    __shared__ ulonglong2 vsm[BK * 16];

    const int qbp = blockIdx.x;   // 0..15
    const int h   = blockIdx.y;   // 0..15
    const int tid = threadIdx.x;

    // balanced pair: (qbp) + (31 - qbp) => constant 130 tiles per CTA
    run_phase(qbp, h, qkv, cache, out, ksm, vsm, tid);
    run_phase(NB - 1 - qbp, h, qkv, cache, out, ksm, vsm, tid);
}

extern "C" void kernel_launch(void* const* d_in, const int* in_sizes, int n_in,
                              void* d_out, int out_size)
{
    const float* qkv   = (const float*)d_in[0];   // [2048, 3072]
    const float* cache = (const float*)d_in[1];   // [1024, 3072]
    float* out = (float*)d_out;                   // [2048, 1024]

    dim3 grid(NPAIR, 16);    // (16 pairs, 16 heads)
    fa2_kernel<<<grid, NTH>>>(qkv, cache, out);
}

// round 5
// speedup vs baseline: 1.9479x; 1.0004x over previous
#include <cuda_runtime.h>

#define T_CACHE 1024
#define ROW3C   3072
#define CEMB    1024
#define BQ      64          // queries per phase
#define BK      32          // keys per smem tile
#define CH      8           // score-chunk size
#define NTH     128
#define NB      32          // number of 64-query blocks (2048/64)
#define NPAIR   16          // balanced pairs

typedef unsigned long long u64;

__device__ __forceinline__ u64 fma2(u64 a, u64 b, u64 c) {
    u64 d; asm("fma.rn.f32x2 %0, %1, %2, %3;" : "=l"(d) : "l"(a), "l"(b), "l"(c)); return d;
}
__device__ __forceinline__ u64 mul2(u64 a, u64 b) {
    u64 d; asm("mul.rn.f32x2 %0, %1, %2;" : "=l"(d) : "l"(a), "l"(b)); return d;
}
__device__ __forceinline__ u64 pack2(float x) {
    u64 d; asm("mov.b64 %0, {%1, %1};" : "=l"(d) : "f"(x)); return d;
}
__device__ __forceinline__ u64 pack2p(float x, float y) {
    u64 d; asm("mov.b64 %0, {%1, %2};" : "=l"(d) : "f"(x), "f"(y)); return d;
}
__device__ __forceinline__ float hadd2(u64 a) {
    float lo, hi; asm("mov.b64 {%0, %1}, %2;" : "=f"(lo), "=f"(hi) : "l"(a)); return lo + hi;
}

// Process one CH-key chunk of the current tile.
template<bool MASK>
__device__ __forceinline__ void do_chunk(
    const ulonglong2* __restrict__ ksm, const ulonglong2* __restrict__ vsm,
    int c0, int s0, int sub, int tq0,
    const u64 q[2][8], u64 acc[2][8], float m[2], float l[2])
{
    float sc[2][CH];

#pragma unroll
    for (int j = 0; j < CH; ++j) {
        const int jj = c0 + j;
        const ulonglong2 ka = ksm[jj * 16 + sub];
        const ulonglong2 kb = ksm[jj * 16 + sub + 4];
        const ulonglong2 kc = ksm[jj * 16 + sub + 8];
        const ulonglong2 kd = ksm[jj * 16 + sub + 12];
#pragma unroll
        for (int qq = 0; qq < 2; ++qq) {
            u64 t = mul2(q[qq][0], ka.x);
            t = fma2(q[qq][1], ka.y, t);
            t = fma2(q[qq][2], kb.x, t);
            t = fma2(q[qq][3], kb.y, t);
            t = fma2(q[qq][4], kc.x, t);
            t = fma2(q[qq][5], kc.y, t);
            t = fma2(q[qq][6], kd.x, t);
            t = fma2(q[qq][7], kd.y, t);
            float s = hadd2(t);
            s += __shfl_xor_sync(0xffffffffu, s, 1);
            s += __shfl_xor_sync(0xffffffffu, s, 2);
            if (MASK)
                sc[qq][j] = (s0 + jj <= tq0 + qq) ? s : -1e30f;
            else
                sc[qq][j] = s;
        }
    }

    // online softmax update
#pragma unroll
    for (int qq = 0; qq < 2; ++qq) {
        float bm = sc[qq][0];
#pragma unroll
        for (int j = 1; j < CH; ++j) bm = fmaxf(bm, sc[qq][j]);
        const float mn = fmaxf(m[qq], bm);
        const float al = __expf(m[qq] - mn);
        m[qq] = mn;
        l[qq] *= al;
        const u64 al2 = pack2(al);
#pragma unroll
        for (int u = 0; u < 8; ++u) acc[qq][u] = mul2(acc[qq][u], al2);
#pragma unroll
        for (int j = 0; j < CH; ++j) {
            const float p = __expf(sc[qq][j] - mn);
            l[qq] += p;
            sc[qq][j] = p;
        }
    }

    // PV accumulate
#pragma unroll
    for (int j = 0; j < CH; ++j) {
        const int jj = c0 + j;
        const ulonglong2 va = vsm[jj * 16 + sub];
        const ulonglong2 vb = vsm[jj * 16 + sub + 4];
        const ulonglong2 vc = vsm[jj * 16 + sub + 8];
        const ulonglong2 vd = vsm[jj * 16 + sub + 12];
#pragma unroll
        for (int qq = 0; qq < 2; ++qq) {
            const u64 p2 = pack2(sc[qq][j]);
            acc[qq][0] = fma2(p2, va.x, acc[qq][0]);
            acc[qq][1] = fma2(p2, va.y, acc[qq][1]);
            acc[qq][2] = fma2(p2, vb.x, acc[qq][2]);
            acc[qq][3] = fma2(p2, vb.y, acc[qq][3]);
            acc[qq][4] = fma2(p2, vc.x, acc[qq][4]);
            acc[qq][5] = fma2(p2, vc.y, acc[qq][5]);
            acc[qq][6] = fma2(p2, vd.x, acc[qq][6]);
            acc[qq][7] = fma2(p2, vd.y, acc[qq][7]);
        }
    }
}

// One 64-query block (one "phase") done by the whole CTA.
__device__ __forceinline__ void run_phase(
    int qb, int h,
    const float* __restrict__ qkv, const float* __restrict__ cache,
    float* __restrict__ out,
    ulonglong2* ksm, ulonglong2* vsm, int tid)
{
    const int sub = tid & 3;      // 16-dim slice: float4 chunks {sub, sub+4, sub+8, sub+12}
    const int grp = tid >> 2;     // 0..31 -> 2 queries each
    const int ql  = qb * BQ + grp * 2;   // local query row (0..2047)
    const int tq0 = T_CACHE + ql;        // global position of qq=0

    // load + pre-scale q
    const float scl = 0.125f;
    u64 q[2][8];
#pragma unroll
    for (int qq = 0; qq < 2; ++qq) {
        const float4* qr = reinterpret_cast<const float4*>(
            qkv + (size_t)(ql + qq) * ROW3C + h * 64);
#pragma unroll
        for (int i = 0; i < 4; ++i) {
            float4 v = qr[sub + 4 * i];
            q[qq][2 * i]     = pack2p(v.x * scl, v.y * scl);
            q[qq][2 * i + 1] = pack2p(v.z * scl, v.w * scl);
        }
    }

    u64 acc[2][8];
#pragma unroll
    for (int qq = 0; qq < 2; ++qq)
#pragma unroll
        for (int u = 0; u < 8; ++u) acc[qq][u] = 0ull;
    float m[2] = {-1e30f, -1e30f};
    float l[2] = {0.f, 0.f};

    const int nkeys  = T_CACHE + qb * BQ + BQ;
    const int ntiles = nkeys / BK;      // exact
    const int nfull  = ntiles - 2;      // last BQ keys need the causal mask

    for (int t = 0; t < ntiles; ++t) {
        const int s0 = t * BK;
        __syncthreads();
        // tiles never straddle the cache/qkv boundary (1024 % 32 == 0)
        const float* base = (s0 < T_CACHE)
            ? (cache + (size_t)s0 * ROW3C)
            : (qkv + (size_t)(s0 - T_CACHE) * ROW3C);
#pragma unroll
        for (int it = 0; it < 4; ++it) {
            const int idx = tid + it * NTH;   // 0..511
            const int row = idx >> 4;
            const int c   = idx & 15;
            const float* rp = base + (size_t)row * ROW3C + h * 64 + c * 4;
            ksm[idx] = *reinterpret_cast<const ulonglong2*>(rp + CEMB);
            vsm[idx] = *reinterpret_cast<const ulonglong2*>(rp + 2 * CEMB);
        }
        __syncthreads();

        if (t < nfull) {
#pragma unroll
            for (int c0 = 0; c0 < BK; c0 += CH)
                do_chunk<false>(ksm, vsm, c0, s0, sub, tq0, q, acc, m, l);
        } else {
#pragma unroll
            for (int c0 = 0; c0 < BK; c0 += CH)
                do_chunk<true>(ksm, vsm, c0, s0, sub, tq0, q, acc, m, l);
        }
    }

    // epilogue
#pragma unroll
    for (int qq = 0; qq < 2; ++qq) {
        const u64 inv2 = pack2(1.f / l[qq]);
        ulonglong2* orow = reinterpret_cast<ulonglong2*>(
            out + (size_t)(ql + qq) * CEMB + h * 64);
#pragma unroll
        for (int i = 0; i < 4; ++i) {
            ulonglong2 o;
            o.x = mul2(acc[qq][2 * i], inv2);
            o.y = mul2(acc[qq][2 * i + 1], inv2);
            orow[sub + 4 * i] = o;
        }
    }
}

__global__ __launch_bounds__(NTH, 3)
void fa2_kernel(const float* __restrict__ qkv,
                const float* __restrict__ cache,
                float* __restrict__ out)
{
    __shared__ ulonglong2 ksm[BK * 16];
    __shared__ ulonglong2 vsm[BK * 16];

    const int qbp = blockIdx.x;   // 0..15
    const int h   = blockIdx.y;   // 0..15
    const int tid = threadIdx.x;

    // balanced pair: (qbp) + (31 - qbp) => constant 130 tiles per CTA
    run_phase(qbp, h, qkv, cache, out, ksm, vsm, tid);
    run_phase(NB - 1 - qbp, h, qkv, cache, out, ksm, vsm, tid);
}

extern "C" void kernel_launch(void* const* d_in, const int* in_sizes, int n_in,
                              void* d_out, int out_size)
{
    const float* qkv   = (const float*)d_in[0];   // [2048, 3072]
    const float* cache = (const float*)d_in[1];   // [1024, 3072]
    float* out = (float*)d_out;                   // [2048, 1024]

    dim3 grid(NPAIR, 16);    // (16 pairs, 16 heads)
    fa2_kernel<<<grid, NTH>>>(qkv, cache, out);
}